// round 14
// baseline (speedup 1.0000x reference)
#include <cuda_runtime.h>

#define TPB 256
#define CPB 256                    // cells per block
#define F4_PER_ARR (CPB * 26 / 4)  // 1664 float4s per array per block (= 128 pairs * 13)

__device__ __forceinline__ float compute_iou(float bx, float by, float bw, float bh,
                                             float lx, float ly, float lw, float lh) {
    const float invS = 1.0f / 7.0f;
    float x1 = bx * invS - bw * 0.5f;
    float y1 = by * invS - bh * 0.5f;
    float x2 = bx * invS + bw * 0.5f;
    float y2 = by * invS + bh * 0.5f;
    float u1 = lx * invS - lw * 0.5f;
    float v1 = ly * invS - lh * 0.5f;
    float u2 = lx * invS + lw * 0.5f;
    float v2 = ly * invS + lh * 0.5f;
    float a1 = (x2 - x1) * (y2 - y1);
    float a2 = (u2 - u1) * (v2 - v1);
    float left   = fmaxf(x1, u1);
    float right  = fminf(x2, u2);
    float top    = fmaxf(y1, v1);
    float bottom = fminf(y2, v2);
    bool valid = (left < right) && (top < bottom);
    float inter = valid ? (right - left) * (bottom - top) : 0.0f;
    float uni = a1 + a2 - inter;
    return valid ? (inter / uni) : 0.0f;
}

// Cold path (~4% of cells): scattered global loads, register pressure isolated.
__device__ __noinline__ float coord_cell_loss(const float* __restrict__ pbase,
                                              const float* __restrict__ lbase,
                                              float p4, float p9) {
    const float2* pp = reinterpret_cast<const float2*>(pbase);
    const float2* lp = reinterpret_cast<const float2*>(lbase);

    float2 p01 = __ldg(pp + 0);
    float2 p23 = __ldg(pp + 1);
    float2 p45 = __ldg(pp + 2);
    float2 p67 = __ldg(pp + 3);
    float2 p89 = __ldg(pp + 4);
    float2 l01 = __ldg(lp + 0);
    float2 l23 = __ldg(lp + 1);

    float cls = 0.0f;
#pragma unroll
    for (int j = 5; j < 13; j++) {
        float2 pv = __ldg(pp + j);
        float2 lv = __ldg(lp + j);
        float dx = pv.x - lv.x;
        float dy = pv.y - lv.y;
        cls += dx * dx + dy * dy;
    }

    float iou1 = compute_iou(p01.x, p01.y, p23.x, p23.y,
                             l01.x, l01.y, l23.x, l23.y);
    float iou2 = compute_iou(p45.y, p67.x, p67.y, p89.x,
                             l01.x, l01.y, l23.x, l23.y);
    bool pick1 = iou1 > iou2;

    float s0 = pick1 ? p01.x : p45.y;
    float s1 = pick1 ? p01.y : p67.x;
    float s2 = pick1 ? p23.x : p67.y;
    float s3 = pick1 ? p23.y : p89.x;

    float d0 = s0 - l01.x;
    float d1 = s1 - l01.y;
    float d2 = sqrtf(s2) - sqrtf(l23.x);
    float d3 = sqrtf(s3) - sqrtf(l23.y);
    float coord_cell = d0 * d0 + d1 * d1 + d2 * d2 + d3 * d3;

    float c  = pick1 ? p4 : p9;
    float io = pick1 ? iou1 : iou2;
    float dc = c - io;
    float obj_c_cell = dc * dc;

    float other = pick1 ? p9 : p4;
    float noobj_extra = other * other;

    return 5.0f * coord_cell + obj_c_cell + 0.5f * noobj_extra + cls;
}

__global__ void __launch_bounds__(TPB, 8)
yolo_kernel(const float* __restrict__ predict,
            const float* __restrict__ label,
            int ncells, float invN,
            float* __restrict__ out) {
    __shared__ float sp4[CPB];
    __shared__ float sp9[CPB];
    __shared__ float sl4[CPB];
    __shared__ float sm[TPB / 32];

    const int tid = threadIdx.x;
    const int cell0 = blockIdx.x * CPB;
    const long long base_f4 = (long long)blockIdx.x * F4_PER_ARR;
    const long long total_f4 = ((long long)ncells * 26) >> 2;

    const float4* P4 = reinterpret_cast<const float4*>(predict);
    const float4* L4 = reinterpret_cast<const float4*>(label);

    // ---- Phase 1: coalesced float4 sweep; 13-float4 period decode ----
    // 2 cells == 13 float4s. For local float4 index i: q = i/13, m = i%13.
    //   m==1: .x = p4(cell 2q)   (+ l4 from label)
    //   m==2: .y = p9(cell 2q)
    //   m==7: .z = p4(cell 2q+1) (+ l4 from label)
    //   m==8: .w = p9(cell 2q+1)
#pragma unroll
    for (int k = 0; k < 7; k++) {
        int i = tid + k * TPB;
        if (i < F4_PER_ARR && base_f4 + i < total_f4) {
            float4 pv = __ldg(P4 + base_f4 + i);
            float4 lv = __ldg(L4 + base_f4 + i);
            unsigned q = (unsigned)i / 13u;          // multiply-shift
            unsigned m = (unsigned)i - 13u * q;
            int c0 = (int)(2u * q);
            if (m == 1u) { sp4[c0]     = pv.x; sl4[c0]     = lv.x; }
            if (m == 2u) { sp9[c0]     = pv.y; }
            if (m == 7u) { sp4[c0 + 1] = pv.z; sl4[c0 + 1] = lv.z; }
            if (m == 8u) { sp9[c0 + 1] = pv.w; }
        }
    }
    __syncthreads();

    // ---- Phase 2: per-cell loss from smem scalars ----
    float loss = 0.0f;
    int cell = cell0 + tid;
    if (cell < ncells) {
        float l4 = sl4[tid];
        float p4 = sp4[tid];
        float p9 = sp9[tid];
        if (l4 == 0.0f) {
            loss = 0.5f * (p4 * p4 + p9 * p9);
        } else {
            loss = coord_cell_loss(predict + (size_t)cell * 26,
                                   label   + (size_t)cell * 26, p4, p9);
        }
    }

    // ---- block reduction ----
    float s = loss;
#pragma unroll
    for (int o = 16; o > 0; o >>= 1)
        s += __shfl_down_sync(0xFFFFFFFFu, s, o);
    if ((tid & 31) == 0)
        sm[tid >> 5] = s;
    __syncthreads();
    if (tid < 32) {
        s = (tid < (TPB / 32)) ? sm[tid] : 0.0f;
#pragma unroll
        for (int o = 16; o > 0; o >>= 1)
            s += __shfl_down_sync(0xFFFFFFFFu, s, o);
        if (tid == 0) {
            float contrib = s * invN;
            asm volatile("red.relaxed.gpu.global.add.f32 [%0], %1;"
                         :: "l"(out), "f"(contrib) : "memory");
        }
    }
}

extern "C" void kernel_launch(void* const* d_in, const int* in_sizes, int n_in,
                              void* d_out, int out_size) {
    const float* predict = (const float*)d_in[0];
    const float* label   = (const float*)d_in[1];
    float* out = (float*)d_out;

    int total  = in_sizes[0];          // B*7*7*26
    int ncells = total / 26;           // B*49
    int nblocks = (ncells + CPB - 1) / CPB;

    float invN = 49.0f / (float)ncells;  // 1 / batch

    cudaMemsetAsync(d_out, 0, sizeof(float), 0);
    yolo_kernel<<<nblocks, TPB>>>(predict, label, ncells, invN, out);
}

// round 15
// speedup vs baseline: 1.7577x; 1.7577x over previous
#include <cuda_runtime.h>

#define TPB 256

__device__ __forceinline__ float compute_iou(float bx, float by, float bw, float bh,
                                             float lx, float ly, float lw, float lh) {
    const float invS = 1.0f / 7.0f;
    float x1 = bx * invS - bw * 0.5f;
    float y1 = by * invS - bh * 0.5f;
    float x2 = bx * invS + bw * 0.5f;
    float y2 = by * invS + bh * 0.5f;
    float u1 = lx * invS - lw * 0.5f;
    float v1 = ly * invS - lh * 0.5f;
    float u2 = lx * invS + lw * 0.5f;
    float v2 = ly * invS + lh * 0.5f;
    float a1 = (x2 - x1) * (y2 - y1);
    float a2 = (u2 - u1) * (v2 - v1);
    float left   = fmaxf(x1, u1);
    float right  = fminf(x2, u2);
    float top    = fmaxf(y1, v1);
    float bottom = fminf(y2, v2);
    bool valid = (left < right) && (top < bottom);
    float inter = valid ? (right - left) * (bottom - top) : 0.0f;
    float uni = a1 + a2 - inter;
    return valid ? (inter / uni) : 0.0f;
}

// Cold path (~4% of cells): scattered global loads, register pressure isolated.
__device__ __noinline__ float coord_cell_loss(const float* __restrict__ pbase,
                                              const float* __restrict__ lbase,
                                              float p4, float p9) {
    const float2* pp = reinterpret_cast<const float2*>(pbase);
    const float2* lp = reinterpret_cast<const float2*>(lbase);

    float2 p01 = __ldg(pp + 0);
    float2 p23 = __ldg(pp + 1);
    float2 p45 = __ldg(pp + 2);
    float2 p67 = __ldg(pp + 3);
    float2 p89 = __ldg(pp + 4);
    float2 l01 = __ldg(lp + 0);
    float2 l23 = __ldg(lp + 1);

    float cls = 0.0f;
#pragma unroll
    for (int j = 5; j < 13; j++) {
        float2 pv = __ldg(pp + j);
        float2 lv = __ldg(lp + j);
        float dx = pv.x - lv.x;
        float dy = pv.y - lv.y;
        cls += dx * dx + dy * dy;
    }

    float iou1 = compute_iou(p01.x, p01.y, p23.x, p23.y,
                             l01.x, l01.y, l23.x, l23.y);
    float iou2 = compute_iou(p45.y, p67.x, p67.y, p89.x,
                             l01.x, l01.y, l23.x, l23.y);
    bool pick1 = iou1 > iou2;

    float s0 = pick1 ? p01.x : p45.y;
    float s1 = pick1 ? p01.y : p67.x;
    float s2 = pick1 ? p23.x : p67.y;
    float s3 = pick1 ? p23.y : p89.x;

    float d0 = s0 - l01.x;
    float d1 = s1 - l01.y;
    float d2 = sqrtf(s2) - sqrtf(l23.x);
    float d3 = sqrtf(s3) - sqrtf(l23.y);
    float coord_cell = d0 * d0 + d1 * d1 + d2 * d2 + d3 * d3;

    float c  = pick1 ? p4 : p9;
    float io = pick1 ? iou1 : iou2;
    float dc = c - io;
    float obj_c_cell = dc * dc;

    float other = pick1 ? p9 : p4;
    float noobj_extra = other * other;

    return 5.0f * coord_cell + obj_c_cell + 0.5f * noobj_extra + cls;
}

// Hot-path per-cell loss; scattered scalar loads (3 per cell).
__device__ __forceinline__ float cell_loss(const float* __restrict__ predict,
                                           const float* __restrict__ label,
                                           int cell) {
    const float* pbase = predict + (size_t)cell * 26;
    const float* lbase = label   + (size_t)cell * 26;

    float l4 = __ldg(lbase + 4);
    float p4 = __ldg(pbase + 4);
    float p9 = __ldg(pbase + 9);

    if (l4 == 0.0f)
        return 0.5f * (p4 * p4 + p9 * p9);
    return coord_cell_loss(pbase, lbase, p4, p9);
}

__global__ void __launch_bounds__(TPB, 8)
yolo_kernel(const float* __restrict__ predict,
            const float* __restrict__ label,
            int ncells, float invN,
            float* __restrict__ out) {
    const int tid = threadIdx.x;
    const int gtid = blockIdx.x * TPB + tid;
    const int stride = gridDim.x * TPB;

    // 2 cells per thread, half-grid stride -> single wave, doubled MLP.
    float loss = 0.0f;
    if (gtid < ncells)          loss  = cell_loss(predict, label, gtid);
    if (gtid + stride < ncells) loss += cell_loss(predict, label, gtid + stride);

    // ---- block reduction ----
    __shared__ float sm[TPB / 32];
    float s = loss;
#pragma unroll
    for (int o = 16; o > 0; o >>= 1)
        s += __shfl_down_sync(0xFFFFFFFFu, s, o);
    if ((tid & 31) == 0)
        sm[tid >> 5] = s;
    __syncthreads();
    if (tid < 32) {
        s = (tid < (TPB / 32)) ? sm[tid] : 0.0f;
#pragma unroll
        for (int o = 16; o > 0; o >>= 1)
            s += __shfl_down_sync(0xFFFFFFFFu, s, o);
        if (tid == 0) {
            // Fire-and-forget no-return reduction into pre-zeroed out[0].
            float contrib = s * invN;
            asm volatile("red.relaxed.gpu.global.add.f32 [%0], %1;"
                         :: "l"(out), "f"(contrib) : "memory");
        }
    }
}

extern "C" void kernel_launch(void* const* d_in, const int* in_sizes, int n_in,
                              void* d_out, int out_size) {
    const float* predict = (const float*)d_in[0];
    const float* label   = (const float*)d_in[1];
    float* out = (float*)d_out;

    int total  = in_sizes[0];          // B*7*7*26
    int ncells = total / 26;           // B*49
    // 2 cells per thread -> half the blocks; 784 for this shape (single wave).
    int nblocks = (ncells + 2 * TPB - 1) / (2 * TPB);

    float invN = 49.0f / (float)ncells;  // 1 / batch

    cudaMemsetAsync(d_out, 0, sizeof(float), 0);
    yolo_kernel<<<nblocks, TPB>>>(predict, label, ncells, invN, out);
}

// round 16
// speedup vs baseline: 1.9221x; 1.0935x over previous
#include <cuda_runtime.h>

#define TPB 256

__device__ __forceinline__ float compute_iou(float bx, float by, float bw, float bh,
                                             float lx, float ly, float lw, float lh) {
    const float invS = 1.0f / 7.0f;
    float x1 = bx * invS - bw * 0.5f;
    float y1 = by * invS - bh * 0.5f;
    float x2 = bx * invS + bw * 0.5f;
    float y2 = by * invS + bh * 0.5f;
    float u1 = lx * invS - lw * 0.5f;
    float v1 = ly * invS - lh * 0.5f;
    float u2 = lx * invS + lw * 0.5f;
    float v2 = ly * invS + lh * 0.5f;
    float a1 = (x2 - x1) * (y2 - y1);
    float a2 = (u2 - u1) * (v2 - v1);
    float left   = fmaxf(x1, u1);
    float right  = fminf(x2, u2);
    float top    = fmaxf(y1, v1);
    float bottom = fminf(y2, v2);
    bool valid = (left < right) && (top < bottom);
    float inter = valid ? (right - left) * (bottom - top) : 0.0f;
    float uni = a1 + a2 - inter;
    return valid ? (inter / uni) : 0.0f;
}

// Cold path (~4% of cells). Loads everything it needs itself (incl. p4/p9).
// Returns the FULL loss for a coord cell.
__device__ __noinline__ float coord_cell_loss(const float* __restrict__ pbase,
                                              const float* __restrict__ lbase) {
    const float2* pp = reinterpret_cast<const float2*>(pbase);
    const float2* lp = reinterpret_cast<const float2*>(lbase);

    float2 p01 = __ldg(pp + 0);
    float2 p23 = __ldg(pp + 1);
    float2 p45 = __ldg(pp + 2);
    float2 p67 = __ldg(pp + 3);
    float2 p89 = __ldg(pp + 4);
    float2 l01 = __ldg(lp + 0);
    float2 l23 = __ldg(lp + 1);

    float cls = 0.0f;
#pragma unroll
    for (int j = 5; j < 13; j++) {
        float2 pv = __ldg(pp + j);
        float2 lv = __ldg(lp + j);
        float dx = pv.x - lv.x;
        float dy = pv.y - lv.y;
        cls += dx * dx + dy * dy;
    }

    float iou1 = compute_iou(p01.x, p01.y, p23.x, p23.y,
                             l01.x, l01.y, l23.x, l23.y);
    float iou2 = compute_iou(p45.y, p67.x, p67.y, p89.x,
                             l01.x, l01.y, l23.x, l23.y);
    bool pick1 = iou1 > iou2;

    float s0 = pick1 ? p01.x : p45.y;
    float s1 = pick1 ? p01.y : p67.x;
    float s2 = pick1 ? p23.x : p67.y;
    float s3 = pick1 ? p23.y : p89.x;

    float d0 = s0 - l01.x;
    float d1 = s1 - l01.y;
    float d2 = sqrtf(s2) - sqrtf(l23.x);
    float d3 = sqrtf(s3) - sqrtf(l23.y);
    float coord_cell = d0 * d0 + d1 * d1 + d2 * d2 + d3 * d3;

    float p4 = p45.x, p9 = p89.y;
    float c  = pick1 ? p4 : p9;
    float io = pick1 ? iou1 : iou2;
    float dc = c - io;
    float obj_c_cell = dc * dc;

    float other = pick1 ? p9 : p4;
    float noobj_extra = other * other;

    return 5.0f * coord_cell + obj_c_cell + 0.5f * noobj_extra + cls;
}

__global__ void __launch_bounds__(TPB, 8)
yolo_kernel(const float* __restrict__ predict,
            const float* __restrict__ label,
            int ncells, float invN,
            float* __restrict__ out) {
    const int tid = threadIdx.x;
    const int lane = tid & 31;
    const int W = blockIdx.x * TPB + (tid & ~31);   // warp's first cell
    const int c0 = W + lane;                         // this thread's own cell

    float loss = 0.0f;

    if (W + 32 <= ncells) {
        // ---- fast path: whole warp in range ----
        // l4 of own cell (26-line scattered load, unavoidable).
        float l4own = __ldg(label + (size_t)c0 * 26 + 4);

        // Pair-loading of predict confs: lanes (2k, 2k+1) load (p4, p9) of the
        // same cell, so each LDG's 32 lanes span only 16 cells = 13 lines.
        int half = lane >> 1;
        int sub  = lane & 1;           // 0 -> p4 (+4), 1 -> p9 (+9)
        int off  = 4 + 5 * sub;
        int cA = W + half;             // cells [W, W+16)
        int cB = W + 16 + half;        // cells [W+16, W+32)
        float vA = __ldg(predict + (size_t)cA * 26 + off);
        float vB = __ldg(predict + (size_t)cB * 26 + off);

        // l4 of the paired cells via shuffle (l4 of cell W+s lives in lane s).
        float l4A = __shfl_sync(0xFFFFFFFFu, l4own, half);
        float l4B = __shfl_sync(0xFFFFFFFFu, l4own, 16 + half);

        if (l4A == 0.0f) loss += 0.5f * vA * vA;
        if (l4B == 0.0f) loss += 0.5f * vB * vB;

        // Coord cells (~4%): full handler on own cell.
        if (l4own > 0.0f)
            loss += coord_cell_loss(predict + (size_t)c0 * 26,
                                    label   + (size_t)c0 * 26);
    } else if (c0 < ncells) {
        // ---- tail fallback: per-cell scalar path ----
        const float* pbase = predict + (size_t)c0 * 26;
        const float* lbase = label   + (size_t)c0 * 26;
        float l4 = __ldg(lbase + 4);
        if (l4 == 0.0f) {
            float p4 = __ldg(pbase + 4);
            float p9 = __ldg(pbase + 9);
            loss = 0.5f * (p4 * p4 + p9 * p9);
        } else {
            loss = coord_cell_loss(pbase, lbase);
        }
    }

    // ---- block reduction ----
    __shared__ float sm[TPB / 32];
    float s = loss;
#pragma unroll
    for (int o = 16; o > 0; o >>= 1)
        s += __shfl_down_sync(0xFFFFFFFFu, s, o);
    if ((tid & 31) == 0)
        sm[tid >> 5] = s;
    __syncthreads();
    if (tid < 32) {
        s = (tid < (TPB / 32)) ? sm[tid] : 0.0f;
#pragma unroll
        for (int o = 16; o > 0; o >>= 1)
            s += __shfl_down_sync(0xFFFFFFFFu, s, o);
        if (tid == 0) {
            // Fire-and-forget no-return reduction into pre-zeroed out[0].
            float contrib = s * invN;
            asm volatile("red.relaxed.gpu.global.add.f32 [%0], %1;"
                         :: "l"(out), "f"(contrib) : "memory");
        }
    }
}

extern "C" void kernel_launch(void* const* d_in, const int* in_sizes, int n_in,
                              void* d_out, int out_size) {
    const float* predict = (const float*)d_in[0];
    const float* label   = (const float*)d_in[1];
    float* out = (float*)d_out;

    int total  = in_sizes[0];          // B*7*7*26
    int ncells = total / 26;           // B*49
    int nblocks = (ncells + TPB - 1) / TPB;

    float invN = 49.0f / (float)ncells;  // 1 / batch

    cudaMemsetAsync(d_out, 0, sizeof(float), 0);
    yolo_kernel<<<nblocks, TPB>>>(predict, label, ncells, invN, out);
}